// round 14
// baseline (speedup 1.0000x reference)
#include <cuda_runtime.h>

#define BATCH  16
#define H      1024
#define HW     (H*H)
#define NSTRIP 11
#define NBANDS 10
#define BANDH  104                     // even; 10*104=1040, last band 88 rows (even)
#define TASKS  (BATCH*NSTRIP*NBANDS)   // 1760
#define WPB    13
#define NT     416
#define NCTA   ((TASKS+WPB-1)/WPB)     // 136
#define WARPF4 1024                    // ring: 32 slots x 32 f4 = 16 KB/warp

__device__ float        g_accum[BATCH * 5];
__device__ unsigned int g_count;

__device__ __forceinline__ float4 f4z() { return make_float4(0.f, 0.f, 0.f, 0.f); }
__device__ __forceinline__ void addf4(float4& a, const float4 b) { a.x+=b.x; a.y+=b.y; a.z+=b.z; a.w+=b.w; }

__device__ __forceinline__ void epi(float x, float m, float S3, float S15, float S31,
                                    float& a0, float& a1, float& a2, float& a3, float& a4)
{
    float w = 1.f + 5.f * ( fabsf(S3  * (1.f / 9.f)   - m)
                          + fabsf(S15 * (1.f / 225.f) - m)
                          + fabsf(S31 * (1.f / 961.f) - m) );
    float e   = __expf(-fabsf(x));
    float l   = __logf(1.f + e);
    float bce = fmaxf(x, 0.f) - x * m + l;
    float inv = __fdividef(1.f, 1.f + e);
    float sg  = (x >= 0.f) ? inv : e * inv;
    a0 += w;
    a1 += w * bce;
    a2 += sg * m * w;
    a3 += (sg + m) * w;
    a4 += fabsf(sg - m);
}

// per-row consume: cross-lane shuffles (uniform) + epilogue
__device__ __forceinline__ void consume_row(
    const float4 U31, const float4 U15, const float4 U3, const float4 Prow, const float4 p,
    bool dataT, float& a0, float& a1, float& a2, float& a3, float& a4)
{
    float a31w = __shfl_down_sync(0xffffffffu, U31.w, 3);
    float b31x = __shfl_down_sync(0xffffffffu, U31.x, 4);
    float b31y = __shfl_down_sync(0xffffffffu, U31.y, 4);
    float b31z = __shfl_down_sync(0xffffffffu, U31.z, 4);
    float c31x = __shfl_up_sync(0xffffffffu, U31.x, 4);
    float c31y = __shfl_up_sync(0xffffffffu, U31.y, 4);
    float c31z = __shfl_up_sync(0xffffffffu, U31.z, 4);
    float c31w = __shfl_up_sync(0xffffffffu, U31.w, 4);
    float a15w = __shfl_down_sync(0xffffffffu, U15.w, 1);
    float b15x = __shfl_down_sync(0xffffffffu, U15.x, 2);
    float b15y = __shfl_down_sync(0xffffffffu, U15.y, 2);
    float b15z = __shfl_down_sync(0xffffffffu, U15.z, 2);
    float c15x = __shfl_up_sync(0xffffffffu, U15.x, 2);
    float c15y = __shfl_up_sync(0xffffffffu, U15.y, 2);
    float c15z = __shfl_up_sync(0xffffffffu, U15.z, 2);
    float c15w = __shfl_up_sync(0xffffffffu, U15.w, 2);
    float uz = __shfl_up_sync(0xffffffffu, U3.z, 1);      // U3(4L-2)
    float uw = __shfl_up_sync(0xffffffffu, U3.w, 1);      // U3(4L-1)
    float dx = __shfl_down_sync(0xffffffffu, U3.x, 1);    // U3(4L+4)
    float mlw = __shfl_up_sync(0xffffffffu, Prow.w, 1);   // P(row)[4L-1]

    if (dataT) {
        float m0 = Prow.x - mlw,    m1 = Prow.y - Prow.x;
        float m2 = Prow.z - Prow.y, m3 = Prow.w - Prow.z;
        epi(p.x, m0, U3.y - uz,   a15w - c15x, a31w - c31x, a0, a1, a2, a3, a4);
        epi(p.y, m1, U3.z - uw,   b15x - c15y, b31x - c31y, a0, a1, a2, a3, a4);
        epi(p.z, m2, U3.w - U3.x, b15y - c15z, b31y - c31z, a0, a1, a2, a3, a4);
        epi(p.w, m3, dx - U3.y,   b15z - c15w, b31z - c31w, a0, a1, a2, a3, a4);
    }
}

__global__ __launch_bounds__(NT, 1) void adaptive_loss_main(
    const float* __restrict__ pred, const float* __restrict__ mask, float* __restrict__ out)
{
    extern __shared__ float4 sm4[];
    unsigned int* sflag = (unsigned int*)(sm4 + WPB * WARPF4);
    const int tid  = threadIdx.x;
    const int lane = tid & 31;
    const int warp = tid >> 5;
    const int task = blockIdx.x * WPB + warp;

    float a0 = 0.f, a1 = 0.f, a2 = 0.f, a3 = 0.f, a4 = 0.f;
    int b = 0;

    if (task < TASKS) {
        b = task / (NSTRIP * NBANDS);
        const int rem  = task % (NSTRIP * NBANDS);
        const int s    = rem / NBANDS;
        const int band = rem % NBANDS;
        const int y0   = band * BANDH;
        const int rows = (H - y0 < BANDH) ? (H - y0) : BANDH;
        const int NI   = rows >> 1;

        const float4* mb4 = (const float4*)(mask + (size_t)b * HW);
        const float4* pb4 = (const float4*)(pred + (size_t)b * HW);

        const int  w     = 24 * s - 4 + lane;
        const bool ok    = ((unsigned)w < 256u);
        const bool dataT = (lane >= 4) && (lane <= 27) && ((24 * s + lane - 4) < 256);

        float4* rg = sm4 + warp * WARPF4;

        float4 U31 = f4z(), U15 = f4z();
        float4 Pm1 = f4z(), P0r = f4z();

        // ---------- priming: rows y0-16 .. y0+14 ----------
        float4 mCur;
        {
            int r = y0 - 16;
            mCur = (r >= 0 && ok) ? mb4[(size_t)r * 256 + w] : f4z();
        }
        #pragma unroll 1
        for (int j = 0; j < 31; ++j) {
            const int r = y0 - 16 + j, rn = r + 1;
            float4 mN = (rn >= 0 && rn < H && ok) ? mb4[(size_t)rn * 256 + w] : f4z();

            float4 v = mCur; v.y += v.x; v.z += v.y; v.w += v.z;
            float tot = v.w;
            #pragma unroll
            for (int d = 1; d < 32; d <<= 1) {
                float u = __shfl_up_sync(0xffffffffu, tot, d);
                if (lane >= d) tot += u;
            }
            const float ex = tot - v.w;
            float4 P = make_float4(v.x + ex, v.y + ex, v.z + ex, v.w + ex);
            rg[((r + 512) & 31) * 32 + lane] = P;

            addf4(U31, P);
            if (j >= 8 && j <= 22) addf4(U15, P);
            if (j == 15) Pm1 = P;                  // P(y0-1)
            if (j == 16) P0r = P;                  // P(y0)

            mCur = mN;
        }
        // mCur = raw mask row y0+15; U31/U15 centered at y0-1
        float4 mCur1 = ((y0 + 16) < H && ok) ? mb4[(size_t)(y0 + 16) * 256 + w] : f4z();

        float4 pCur0 = dataT ? pb4[(size_t)y0 * 256 + w] : f4z();
        float4 pCur1 = dataT ? pb4[(size_t)(y0 + 1) * 256 + w] : f4z();

        // ---------- main: NI iterations, 2 rows each ----------
        #pragma unroll 1
        for (int i = 0; i < NI; ++i) {
            const int y = y0 + 2 * i;
            const int ra = y + 17, rb = y + 18;
            float4 mN0 = (ra < H && ok) ? mb4[(size_t)ra * 256 + w] : f4z();
            float4 mN1 = (rb < H && ok) ? mb4[(size_t)rb * 256 + w] : f4z();
            float4 pN0 = (dataT && (y + 2 < H)) ? pb4[(size_t)(y + 2) * 256 + w] : f4z();
            float4 pN1 = (dataT && (y + 3 < H)) ? pb4[(size_t)(y + 3) * 256 + w] : f4z();

            // dual interleaved scans of rows y+15, y+16
            float4 v0 = mCur;  v0.y += v0.x; v0.z += v0.y; v0.w += v0.z;
            float4 v1 = mCur1; v1.y += v1.x; v1.z += v1.y; v1.w += v1.z;
            float t0 = v0.w, t1s = v1.w;
            #pragma unroll
            for (int d = 1; d < 32; d <<= 1) {
                float u0 = __shfl_up_sync(0xffffffffu, t0, d);
                float u1 = __shfl_up_sync(0xffffffffu, t1s, d);
                if (lane >= d) { t0 += u0; t1s += u1; }
            }
            const float ex0 = t0 - v0.w, ex1 = t1s - v1.w;
            float4 P0s = make_float4(v0.x + ex0, v0.y + ex0, v0.z + ex0, v0.w + ex0);
            float4 P1s = make_float4(v1.x + ex1, v1.y + ex1, v1.z + ex1, v1.w + ex1);

            // taps (ALL reads before any write; own-lane)
            float4 t16a = rg[((y - 16 + 512) & 31) * 32 + lane];
            float4 t7a  = rg[((y + 7)        & 31) * 32 + lane];
            float4 t8a  = rg[((y - 8 + 512)  & 31) * 32 + lane];
            float4 P1r  = rg[((y + 1)        & 31) * 32 + lane];   // P(y+1)
            float4 t16b = rg[((y - 15 + 512) & 31) * 32 + lane];
            float4 t7b  = rg[((y + 8)        & 31) * 32 + lane];
            float4 t8b  = rg[((y - 7 + 512)  & 31) * 32 + lane];
            float4 P2r  = rg[((y + 2)        & 31) * 32 + lane];   // P(y+2)

            rg[((y + 15) & 31) * 32 + lane] = P0s;
            rg[((y + 16) & 31) * 32 + lane] = P1s;

            float4 U31a, U31b, U15a, U15b, U3a, U3b;
            U31a.x = U31.x + P0s.x - t16a.x; U31a.y = U31.y + P0s.y - t16a.y;
            U31a.z = U31.z + P0s.z - t16a.z; U31a.w = U31.w + P0s.w - t16a.w;
            U31b.x = U31a.x + P1s.x - t16b.x; U31b.y = U31a.y + P1s.y - t16b.y;
            U31b.z = U31a.z + P1s.z - t16b.z; U31b.w = U31a.w + P1s.w - t16b.w;
            U15a.x = U15.x + t7a.x - t8a.x; U15a.y = U15.y + t7a.y - t8a.y;
            U15a.z = U15.z + t7a.z - t8a.z; U15a.w = U15.w + t7a.w - t8a.w;
            U15b.x = U15a.x + t7b.x - t8b.x; U15b.y = U15a.y + t7b.y - t8b.y;
            U15b.z = U15a.z + t7b.z - t8b.z; U15b.w = U15a.w + t7b.w - t8b.w;
            U31 = U31b; U15 = U15b;

            U3a.x = Pm1.x + P0r.x + P1r.x; U3a.y = Pm1.y + P0r.y + P1r.y;
            U3a.z = Pm1.z + P0r.z + P1r.z; U3a.w = Pm1.w + P0r.w + P1r.w;
            U3b.x = P0r.x + P1r.x + P2r.x; U3b.y = P0r.y + P1r.y + P2r.y;
            U3b.z = P0r.z + P1r.z + P2r.z; U3b.w = P0r.w + P1r.w + P2r.w;

            consume_row(U31a, U15a, U3a, P0r, pCur0, dataT, a0, a1, a2, a3, a4);
            consume_row(U31b, U15b, U3b, P1r, pCur1, dataT, a0, a1, a2, a3, a4);

            Pm1 = P1r; P0r = P2r;
            mCur = mN0; mCur1 = mN1;
            pCur0 = pN0; pCur1 = pN1;
        }

        // warp reduce + per-warp atomics
        #pragma unroll
        for (int d = 16; d > 0; d >>= 1) {
            a0 += __shfl_down_sync(0xffffffffu, a0, d);
            a1 += __shfl_down_sync(0xffffffffu, a1, d);
            a2 += __shfl_down_sync(0xffffffffu, a2, d);
            a3 += __shfl_down_sync(0xffffffffu, a3, d);
            a4 += __shfl_down_sync(0xffffffffu, a4, d);
        }
        if (lane == 0) {
            atomicAdd(&g_accum[b * 5 + 0], a0);
            atomicAdd(&g_accum[b * 5 + 1], a1);
            atomicAdd(&g_accum[b * 5 + 2], a2);
            atomicAdd(&g_accum[b * 5 + 3], a3);
            atomicAdd(&g_accum[b * 5 + 4], a4);
        }
    }

    // ---- last-block finalize ----
    __threadfence();
    __syncthreads();
    if (tid == 0) {
        unsigned int cdone = atomicAdd(&g_count, 1u);
        *sflag = (cdone == (unsigned int)(gridDim.x - 1)) ? 1u : 0u;
    }
    __syncthreads();
    if (*sflag && tid == 0) {
        float vals[BATCH * 5];
        #pragma unroll 1
        for (int i = 0; i < BATCH * 5; ++i) vals[i] = atomicAdd(&g_accum[i], 0.f);
        float mae_total = 0.f;
        for (int bb = 0; bb < BATCH; ++bb) mae_total += vals[bb * 5 + 4];
        const float mae = mae_total / (float)((long long)BATCH * HW);
        float acc = 0.f;
        for (int bb = 0; bb < BATCH; ++bb) {
            float ws = vals[bb * 5 + 0];
            float wb = vals[bb * 5 + 1];
            float it = vals[bb * 5 + 2];
            float un = vals[bb * 5 + 3];
            float wbce = wb / ws;
            float wiou = 1.f - (it + 1.f) / (un - it + 1.f);
            float wmae = mae * ws / (ws - (float)HW);
            acc += 0.7f * (wbce + wiou + wmae);
        }
        out[0] = acc / (float)BATCH;
        #pragma unroll 1
        for (int i = 0; i < BATCH * 5; ++i) g_accum[i] = 0.f;
        __threadfence();
        atomicExch(&g_count, 0u);
    }
}

extern "C" void kernel_launch(void* const* d_in, const int* in_sizes, int n_in,
                              void* d_out, int out_size) {
    const float* pred = (const float*)d_in[0];
    const float* mask = (const float*)d_in[1];
    float* out = (float*)d_out;

    const int smem_bytes = WPB * WARPF4 * 16 + 16;
    cudaFuncSetAttribute(adaptive_loss_main,
                         cudaFuncAttributeMaxDynamicSharedMemorySize, smem_bytes);
    adaptive_loss_main<<<NCTA, NT, smem_bytes>>>(pred, mask, out);
}

// round 15
// speedup vs baseline: 1.1125x; 1.1125x over previous
#include <cuda_runtime.h>

#define BATCH  16
#define H      1024
#define HW     (H*H)
#define NSTRIP 11
#define NBANDS 10
#define BANDH  103
#define TASKS  (BATCH*NSTRIP*NBANDS)   // 1760
#define WPB    12
#define NT     384
#define NCTA   ((TASKS+WPB-1)/WPB)     // 147
#define WARPF4 1024                    // ring: 32 slots x 32 f4 = 16 KB/warp

__device__ float        g_accum[BATCH * 5];
__device__ unsigned int g_count;

__device__ __forceinline__ float4 f4z() { return make_float4(0.f, 0.f, 0.f, 0.f); }
__device__ __forceinline__ void addf4(float4& a, const float4 b) { a.x+=b.x; a.y+=b.y; a.z+=b.z; a.w+=b.w; }

__device__ __forceinline__ void epi(float x, float m, float S3, float S15, float S31,
                                    float& a0, float& a1, float& a2, float& a3, float& a4)
{
    float w = 1.f + 5.f * ( fabsf(S3  * (1.f / 9.f)   - m)
                          + fabsf(S15 * (1.f / 225.f) - m)
                          + fabsf(S31 * (1.f / 961.f) - m) );
    float e   = __expf(-fabsf(x));
    float l   = __logf(1.f + e);
    float bce = fmaxf(x, 0.f) - x * m + l;
    float inv = __fdividef(1.f, 1.f + e);
    float sg  = (x >= 0.f) ? inv : e * inv;
    a0 += w;
    a1 += w * bce;
    a2 += sg * m * w;
    a3 += (sg + m) * w;
    a4 += fabsf(sg - m);
}

// consume one row: cross-lane shuffles (uniform) + epilogue. State passed by value.
__device__ __forceinline__ void consume_row(
    const float4 U31, const float4 U15, const float4 U3, const float4 Prow, const float4 p,
    bool dataT, float& a0, float& a1, float& a2, float& a3, float& a4)
{
    float a31w = __shfl_down_sync(0xffffffffu, U31.w, 3);
    float b31x = __shfl_down_sync(0xffffffffu, U31.x, 4);
    float b31y = __shfl_down_sync(0xffffffffu, U31.y, 4);
    float b31z = __shfl_down_sync(0xffffffffu, U31.z, 4);
    float c31x = __shfl_up_sync(0xffffffffu, U31.x, 4);
    float c31y = __shfl_up_sync(0xffffffffu, U31.y, 4);
    float c31z = __shfl_up_sync(0xffffffffu, U31.z, 4);
    float c31w = __shfl_up_sync(0xffffffffu, U31.w, 4);
    float a15w = __shfl_down_sync(0xffffffffu, U15.w, 1);
    float b15x = __shfl_down_sync(0xffffffffu, U15.x, 2);
    float b15y = __shfl_down_sync(0xffffffffu, U15.y, 2);
    float b15z = __shfl_down_sync(0xffffffffu, U15.z, 2);
    float c15x = __shfl_up_sync(0xffffffffu, U15.x, 2);
    float c15y = __shfl_up_sync(0xffffffffu, U15.y, 2);
    float c15z = __shfl_up_sync(0xffffffffu, U15.z, 2);
    float c15w = __shfl_up_sync(0xffffffffu, U15.w, 2);
    float uz = __shfl_up_sync(0xffffffffu, U3.z, 1);      // U3(4L-2)
    float uw = __shfl_up_sync(0xffffffffu, U3.w, 1);      // U3(4L-1)
    float dx = __shfl_down_sync(0xffffffffu, U3.x, 1);    // U3(4L+4)
    float mlw = __shfl_up_sync(0xffffffffu, Prow.w, 1);   // P(row)[4L-1]

    if (dataT) {
        float m0 = Prow.x - mlw,    m1 = Prow.y - Prow.x;
        float m2 = Prow.z - Prow.y, m3 = Prow.w - Prow.z;
        epi(p.x, m0, U3.y - uz,   a15w - c15x, a31w - c31x, a0, a1, a2, a3, a4);
        epi(p.y, m1, U3.z - uw,   b15x - c15y, b31x - c31y, a0, a1, a2, a3, a4);
        epi(p.z, m2, U3.w - U3.x, b15y - c15z, b31y - c31z, a0, a1, a2, a3, a4);
        epi(p.w, m3, dx - U3.y,   b15z - c15w, b31z - c31w, a0, a1, a2, a3, a4);
    }
}

__global__ __launch_bounds__(NT, 1) void adaptive_loss_main(
    const float* __restrict__ pred, const float* __restrict__ mask, float* __restrict__ out)
{
    extern __shared__ float4 sm4[];
    unsigned int* sflag = (unsigned int*)(sm4 + WPB * WARPF4);
    const int tid  = threadIdx.x;
    const int lane = tid & 31;
    const int warp = tid >> 5;
    const int task = blockIdx.x * WPB + warp;

    float a0 = 0.f, a1 = 0.f, a2 = 0.f, a3 = 0.f, a4 = 0.f;
    int b = 0;

    if (task < TASKS) {
        b = task / (NSTRIP * NBANDS);
        const int rem  = task % (NSTRIP * NBANDS);
        const int s    = rem / NBANDS;
        const int band = rem % NBANDS;
        const int y0   = band * BANDH;
        const int rows = (H - y0 < BANDH) ? (H - y0) : BANDH;

        const float4* mb4 = (const float4*)(mask + (size_t)b * HW);
        const float4* pb4 = (const float4*)(pred + (size_t)b * HW);

        const int  w     = 24 * s - 4 + lane;     // global f4 word
        const bool ok    = ((unsigned)w < 256u);
        const bool dataT = (lane >= 4) && (lane <= 27) && ((24 * s + lane - 4) < 256);

        float4* rg = sm4 + warp * WARPF4;         // per-warp, per-lane ring: slot*32 + lane

        float4 U31 = f4z(), U15 = f4z(), U3 = f4z();

        // ---------- priming: rows y0-16 .. y0+14 ----------
        float4 mCur;
        {
            int r = y0 - 16;
            mCur = (r >= 0 && ok) ? mb4[(size_t)r * 256 + w] : f4z();
        }
        float4 mP = f4z(), mPm1 = f4z(), mPm2 = f4z();
        #pragma unroll 1
        for (int j = 0; j < 31; ++j) {
            const int r = y0 - 16 + j, rn = r + 1;
            float4 mN = (rn >= 0 && rn < H && ok) ? mb4[(size_t)rn * 256 + w] : f4z();

            float4 v = mCur; v.y += v.x; v.z += v.y; v.w += v.z;
            float tot = v.w;
            #pragma unroll
            for (int d = 1; d < 32; d <<= 1) {
                float u = __shfl_up_sync(0xffffffffu, tot, d);
                if (lane >= d) tot += u;
            }
            const float ex = tot - v.w;
            float4 P = make_float4(v.x + ex, v.y + ex, v.z + ex, v.w + ex);
            rg[((r + 512) & 31) * 32 + lane] = P;

            addf4(U31, P);
            if (j >= 8  && j <= 22) addf4(U15, P);
            if (j >= 14 && j <= 16) addf4(U3,  P);
            if (j == 14) mPm2 = P;                 // P(y0-2)
            if (j == 15) mPm1 = P;                 // P(y0-1)
            if (j == 16) mP   = P;                 // P(y0)

            mCur = mN;
        }
        // mCur = raw mask row y0+15; U centered at y0-1

        float4 pCur  = dataT ? pb4[(size_t)y0 * 256 + w] : f4z();
        float4 pPrev = f4z();

        // ---------- main: consume row y-1 (registers), build row y ----------
        #pragma unroll 1
        for (int i = 0; i < rows; ++i) {
            const int y  = y0 + i;
            const int rn = y + 16;
            float4 mN = (rn < H && ok) ? mb4[(size_t)rn * 256 + w] : f4z();
            float4 pN = (dataT && (y + 1 < H)) ? pb4[(size_t)(y + 1) * 256 + w] : f4z();

            // consume row y-1 from register state (overlaps with scan below)
            if (i > 0)
                consume_row(U31, U15, U3, mPm1, pPrev, dataT, a0, a1, a2, a3, a4);

            // warp-local scan of mask row y+15
            float4 v = mCur; v.y += v.x; v.z += v.y; v.w += v.z;
            float tot = v.w;
            #pragma unroll
            for (int d = 1; d < 32; d <<= 1) {
                float u = __shfl_up_sync(0xffffffffu, tot, d);
                if (lane >= d) tot += u;
            }
            const float ex = tot - v.w;
            float4 P = make_float4(v.x + ex, v.y + ex, v.z + ex, v.w + ex);
            rg[((y + 15) & 31) * 32 + lane] = P;

            // own-lane ring taps
            float4 t16 = rg[((y - 16 + 512) & 31) * 32 + lane];
            float4 t7  = rg[((y + 7)        & 31) * 32 + lane];
            float4 t8  = rg[((y - 8 + 512)  & 31) * 32 + lane];
            float4 t1  = rg[((y + 1)        & 31) * 32 + lane];

            U31.x += P.x - t16.x; U31.y += P.y - t16.y; U31.z += P.z - t16.z; U31.w += P.w - t16.w;
            U15.x += t7.x - t8.x; U15.y += t7.y - t8.y; U15.z += t7.z - t8.z; U15.w += t7.w - t8.w;
            U3.x  += t1.x - mPm2.x; U3.y += t1.y - mPm2.y; U3.z += t1.z - mPm2.z; U3.w += t1.w - mPm2.w;

            mPm2 = mPm1; mPm1 = mP; mP = t1;       // rotate P pipeline
            pPrev = pCur; pCur = pN;
            mCur = mN;
        }

        // tail: consume row y0+rows-1
        consume_row(U31, U15, U3, mPm1, pPrev, dataT, a0, a1, a2, a3, a4);

        // warp reduce + per-warp atomics
        #pragma unroll
        for (int d = 16; d > 0; d >>= 1) {
            a0 += __shfl_down_sync(0xffffffffu, a0, d);
            a1 += __shfl_down_sync(0xffffffffu, a1, d);
            a2 += __shfl_down_sync(0xffffffffu, a2, d);
            a3 += __shfl_down_sync(0xffffffffu, a3, d);
            a4 += __shfl_down_sync(0xffffffffu, a4, d);
        }
        if (lane == 0) {
            atomicAdd(&g_accum[b * 5 + 0], a0);
            atomicAdd(&g_accum[b * 5 + 1], a1);
            atomicAdd(&g_accum[b * 5 + 2], a2);
            atomicAdd(&g_accum[b * 5 + 3], a3);
            atomicAdd(&g_accum[b * 5 + 4], a4);
        }
    }

    // ---- last-block finalize ----
    __threadfence();
    __syncthreads();
    if (tid == 0) {
        unsigned int cdone = atomicAdd(&g_count, 1u);
        *sflag = (cdone == (unsigned int)(gridDim.x - 1)) ? 1u : 0u;
    }
    __syncthreads();
    if (*sflag && tid == 0) {
        float vals[BATCH * 5];
        #pragma unroll 1
        for (int i = 0; i < BATCH * 5; ++i) vals[i] = atomicAdd(&g_accum[i], 0.f);
        float mae_total = 0.f;
        for (int bb = 0; bb < BATCH; ++bb) mae_total += vals[bb * 5 + 4];
        const float mae = mae_total / (float)((long long)BATCH * HW);
        float acc = 0.f;
        for (int bb = 0; bb < BATCH; ++bb) {
            float ws = vals[bb * 5 + 0];
            float wb = vals[bb * 5 + 1];
            float it = vals[bb * 5 + 2];
            float un = vals[bb * 5 + 3];
            float wbce = wb / ws;
            float wiou = 1.f - (it + 1.f) / (un - it + 1.f);
            float wmae = mae * ws / (ws - (float)HW);
            acc += 0.7f * (wbce + wiou + wmae);
        }
        out[0] = acc / (float)BATCH;
        #pragma unroll 1
        for (int i = 0; i < BATCH * 5; ++i) g_accum[i] = 0.f;
        __threadfence();
        atomicExch(&g_count, 0u);
    }
}

extern "C" void kernel_launch(void* const* d_in, const int* in_sizes, int n_in,
                              void* d_out, int out_size) {
    const float* pred = (const float*)d_in[0];
    const float* mask = (const float*)d_in[1];
    float* out = (float*)d_out;

    const int smem_bytes = WPB * WARPF4 * 16 + 16;
    cudaFuncSetAttribute(adaptive_loss_main,
                         cudaFuncAttributeMaxDynamicSharedMemorySize, smem_bytes);
    adaptive_loss_main<<<NCTA, NT, smem_bytes>>>(pred, mask, out);
}

// round 16
// speedup vs baseline: 1.1185x; 1.0054x over previous
#include <cuda_runtime.h>

#define BATCH  16
#define H      1024
#define HW     (H*H)
#define NSTRIP 11
#define NBANDS 10
#define BANDH  103
#define TASKS  (BATCH*NSTRIP*NBANDS)   // 1760
#define WPB    12
#define NT     384
#define NCTA   ((TASKS+WPB-1)/WPB)     // 147
#define WARPF4 1024                    // ring: 32 slots x 32 f4 = 16 KB/warp

__device__ float        g_accum[BATCH * 5];
__device__ unsigned int g_count;

__device__ __forceinline__ float4 f4z() { return make_float4(0.f, 0.f, 0.f, 0.f); }
__device__ __forceinline__ void addf4(float4& a, const float4 b) { a.x+=b.x; a.y+=b.y; a.z+=b.z; a.w+=b.w; }

__device__ __forceinline__ void epi(float x, float m, float S3, float S15, float S31,
                                    float& a0, float& a1, float& a2, float& a3, float& a4)
{
    float w = 1.f + 5.f * ( fabsf(S3  * (1.f / 9.f)   - m)
                          + fabsf(S15 * (1.f / 225.f) - m)
                          + fabsf(S31 * (1.f / 961.f) - m) );
    float e   = __expf(-fabsf(x));
    float l   = __logf(1.f + e);
    float bce = fmaxf(x, 0.f) - x * m + l;
    float inv = __fdividef(1.f, 1.f + e);
    float sg  = (x >= 0.f) ? inv : e * inv;
    a0 += w;
    a1 += w * bce;
    a2 += sg * m * w;
    a3 += (sg + m) * w;
    a4 += fabsf(sg - m);
}

__global__ __launch_bounds__(NT, 1) void adaptive_loss_main(
    const float* __restrict__ pred, const float* __restrict__ mask, float* __restrict__ out)
{
    extern __shared__ float4 sm4[];
    unsigned int* sflag = (unsigned int*)(sm4 + WPB * WARPF4);
    const int tid  = threadIdx.x;
    const int lane = tid & 31;
    const int warp = tid >> 5;
    const int task = blockIdx.x * WPB + warp;

    float a0 = 0.f, a1 = 0.f, a2 = 0.f, a3 = 0.f, a4 = 0.f;
    int b = 0;

    if (task < TASKS) {
        b = task / (NSTRIP * NBANDS);
        const int rem  = task % (NSTRIP * NBANDS);
        const int s    = rem / NBANDS;
        const int band = rem % NBANDS;
        const int y0   = band * BANDH;
        const int rows = (H - y0 < BANDH) ? (H - y0) : BANDH;

        const float4* mb4 = (const float4*)(mask + (size_t)b * HW);
        const float4* pb4 = (const float4*)(pred + (size_t)b * HW);

        const int  w     = 24 * s - 4 + lane;     // global f4 word
        const bool ok    = ((unsigned)w < 256u);
        const bool dataT = (lane >= 4) && (lane <= 27) && ((24 * s + lane - 4) < 256);

        float4* rg = sm4 + warp * WARPF4;         // per-warp, per-lane ring: slot*32 + lane

        float4 U31 = f4z(), U15 = f4z(), U3 = f4z();

        // ---------- priming: rows y0-16 .. y0+14 ----------
        float4 mCur;
        {
            int r = y0 - 16;
            mCur = (r >= 0 && ok) ? mb4[(size_t)r * 256 + w] : f4z();
        }
        float4 mP = f4z(), mPm1 = f4z(), mPm2 = f4z();
        #pragma unroll 1
        for (int j = 0; j < 31; ++j) {
            const int r = y0 - 16 + j, rn = r + 1;
            float4 mN = (rn >= 0 && rn < H && ok) ? mb4[(size_t)rn * 256 + w] : f4z();

            float4 v = mCur; v.y += v.x; v.z += v.y; v.w += v.z;
            float tot = v.w;
            #pragma unroll
            for (int d = 1; d < 32; d <<= 1) {
                float u = __shfl_up_sync(0xffffffffu, tot, d);
                if (lane >= d) tot += u;
            }
            const float ex = tot - v.w;
            float4 P = make_float4(v.x + ex, v.y + ex, v.z + ex, v.w + ex);
            rg[((r + 512) & 31) * 32 + lane] = P;

            addf4(U31, P);
            if (j >= 8  && j <= 22) addf4(U15, P);
            if (j >= 14 && j <= 16) addf4(U3,  P);
            if (j == 14) mPm2 = P;                 // P(y0-2)
            if (j == 15) mPm1 = P;                 // P(y0-1)
            if (j == 16) mP   = P;                 // P(y0)

            mCur = mN;
        }
        // mCur = raw mask row y0+15; U centered at y0-1

        // ---------- deep prefetch FIFOs (depth 3) ----------
        float4 m1 = ((y0 + 16) < H && ok) ? mb4[(size_t)(y0 + 16) * 256 + w] : f4z();
        float4 m2 = ((y0 + 17) < H && ok) ? mb4[(size_t)(y0 + 17) * 256 + w] : f4z();
        float4 pCur = dataT ? pb4[(size_t)y0 * 256 + w] : f4z();
        float4 p1 = (dataT && (y0 + 1) < H) ? pb4[(size_t)(y0 + 1) * 256 + w] : f4z();
        float4 p2 = (dataT && (y0 + 2) < H) ? pb4[(size_t)(y0 + 2) * 256 + w] : f4z();

        // ---------- main: consume row y in the same iteration ----------
        #pragma unroll 1
        for (int i = 0; i < rows; ++i) {
            const int y   = y0 + i;
            const int rmn = y + 18, rpn = y + 3;
            float4 mN = (rmn < H && ok) ? mb4[(size_t)rmn * 256 + w] : f4z();
            float4 pN = (dataT && rpn < H) ? pb4[(size_t)rpn * 256 + w] : f4z();

            // warp-local scan of mask row y+15 (mCur loaded 3 iterations ago)
            float4 v = mCur; v.y += v.x; v.z += v.y; v.w += v.z;
            float tot = v.w;
            #pragma unroll
            for (int d = 1; d < 32; d <<= 1) {
                float u = __shfl_up_sync(0xffffffffu, tot, d);
                if (lane >= d) tot += u;
            }
            const float ex = tot - v.w;
            float4 P = make_float4(v.x + ex, v.y + ex, v.z + ex, v.w + ex);
            rg[((y + 15) & 31) * 32 + lane] = P;

            // own-lane ring taps
            float4 t16 = rg[((y - 16 + 512) & 31) * 32 + lane];
            float4 t7  = rg[((y + 7)        & 31) * 32 + lane];
            float4 t8  = rg[((y - 8 + 512)  & 31) * 32 + lane];
            float4 t1  = rg[((y + 1)        & 31) * 32 + lane];

            U31.x += P.x - t16.x; U31.y += P.y - t16.y; U31.z += P.z - t16.z; U31.w += P.w - t16.w;
            U15.x += t7.x - t8.x; U15.y += t7.y - t8.y; U15.z += t7.z - t8.z; U15.w += t7.w - t8.w;
            U3.x  += t1.x - mPm2.x; U3.y += t1.y - mPm2.y; U3.z += t1.z - mPm2.z; U3.w += t1.w - mPm2.w;

            // cross-lane values via register shuffles (uniform execution)
            float a31w = __shfl_down_sync(0xffffffffu, U31.w, 3);
            float b31x = __shfl_down_sync(0xffffffffu, U31.x, 4);
            float b31y = __shfl_down_sync(0xffffffffu, U31.y, 4);
            float b31z = __shfl_down_sync(0xffffffffu, U31.z, 4);
            float c31x = __shfl_up_sync(0xffffffffu, U31.x, 4);
            float c31y = __shfl_up_sync(0xffffffffu, U31.y, 4);
            float c31z = __shfl_up_sync(0xffffffffu, U31.z, 4);
            float c31w = __shfl_up_sync(0xffffffffu, U31.w, 4);
            float a15w = __shfl_down_sync(0xffffffffu, U15.w, 1);
            float b15x = __shfl_down_sync(0xffffffffu, U15.x, 2);
            float b15y = __shfl_down_sync(0xffffffffu, U15.y, 2);
            float b15z = __shfl_down_sync(0xffffffffu, U15.z, 2);
            float c15x = __shfl_up_sync(0xffffffffu, U15.x, 2);
            float c15y = __shfl_up_sync(0xffffffffu, U15.y, 2);
            float c15z = __shfl_up_sync(0xffffffffu, U15.z, 2);
            float c15w = __shfl_up_sync(0xffffffffu, U15.w, 2);
            float uz = __shfl_up_sync(0xffffffffu, U3.z, 1);      // U3(4L-2)
            float uw = __shfl_up_sync(0xffffffffu, U3.w, 1);      // U3(4L-1)
            float dx = __shfl_down_sync(0xffffffffu, U3.x, 1);    // U3(4L+4)
            float mlw = __shfl_up_sync(0xffffffffu, mP.w, 1);     // P(y)[4L-1]

            if (dataT) {
                float m0 = mP.x - mlw,  m1v = mP.y - mP.x;
                float m2v = mP.z - mP.y, m3 = mP.w - mP.z;

                epi(pCur.x, m0,  U3.y - uz,   a15w - c15x, a31w - c31x, a0, a1, a2, a3, a4);
                epi(pCur.y, m1v, U3.z - uw,   b15x - c15y, b31x - c31y, a0, a1, a2, a3, a4);
                epi(pCur.z, m2v, U3.w - U3.x, b15y - c15z, b31y - c31z, a0, a1, a2, a3, a4);
                epi(pCur.w, m3,  dx - U3.y,   b15z - c15w, b31z - c31w, a0, a1, a2, a3, a4);
            }

            mPm2 = mPm1; mPm1 = mP; mP = t1;       // rotate P(y-2),P(y-1),P(y) pipeline
            mCur = m1; m1 = m2; m2 = mN;           // mask FIFO (depth 3)
            pCur = p1; p1 = p2; p2 = pN;           // pred FIFO (depth 3)
        }

        // warp reduce + per-warp atomics
        #pragma unroll
        for (int d = 16; d > 0; d >>= 1) {
            a0 += __shfl_down_sync(0xffffffffu, a0, d);
            a1 += __shfl_down_sync(0xffffffffu, a1, d);
            a2 += __shfl_down_sync(0xffffffffu, a2, d);
            a3 += __shfl_down_sync(0xffffffffu, a3, d);
            a4 += __shfl_down_sync(0xffffffffu, a4, d);
        }
        if (lane == 0) {
            atomicAdd(&g_accum[b * 5 + 0], a0);
            atomicAdd(&g_accum[b * 5 + 1], a1);
            atomicAdd(&g_accum[b * 5 + 2], a2);
            atomicAdd(&g_accum[b * 5 + 3], a3);
            atomicAdd(&g_accum[b * 5 + 4], a4);
        }
    }

    // ---- last-block finalize ----
    __threadfence();
    __syncthreads();
    if (tid == 0) {
        unsigned int cdone = atomicAdd(&g_count, 1u);
        *sflag = (cdone == (unsigned int)(gridDim.x - 1)) ? 1u : 0u;
    }
    __syncthreads();
    if (*sflag && tid == 0) {
        float vals[BATCH * 5];
        #pragma unroll 1
        for (int i = 0; i < BATCH * 5; ++i) vals[i] = atomicAdd(&g_accum[i], 0.f);
        float mae_total = 0.f;
        for (int bb = 0; bb < BATCH; ++bb) mae_total += vals[bb * 5 + 4];
        const float mae = mae_total / (float)((long long)BATCH * HW);
        float acc = 0.f;
        for (int bb = 0; bb < BATCH; ++bb) {
            float ws = vals[bb * 5 + 0];
            float wb = vals[bb * 5 + 1];
            float it = vals[bb * 5 + 2];
            float un = vals[bb * 5 + 3];
            float wbce = wb / ws;
            float wiou = 1.f - (it + 1.f) / (un - it + 1.f);
            float wmae = mae * ws / (ws - (float)HW);
            acc += 0.7f * (wbce + wiou + wmae);
        }
        out[0] = acc / (float)BATCH;
        #pragma unroll 1
        for (int i = 0; i < BATCH * 5; ++i) g_accum[i] = 0.f;
        __threadfence();
        atomicExch(&g_count, 0u);
    }
}

extern "C" void kernel_launch(void* const* d_in, const int* in_sizes, int n_in,
                              void* d_out, int out_size) {
    const float* pred = (const float*)d_in[0];
    const float* mask = (const float*)d_in[1];
    float* out = (float*)d_out;

    const int smem_bytes = WPB * WARPF4 * 16 + 16;
    cudaFuncSetAttribute(adaptive_loss_main,
                         cudaFuncAttributeMaxDynamicSharedMemorySize, smem_bytes);
    adaptive_loss_main<<<NCTA, NT, smem_bytes>>>(pred, mask, out);
}